// round 1
// baseline (speedup 1.0000x reference)
#include <cuda_runtime.h>

#define B  8
#define D  512
#define T  8192
#define CS 16
#define TC 512   // T / CS
#define DH 64    // D / 8

// Scratch (no cudaMalloc allowed)
__device__ float g_pooled[B * D * TC];          // 8 MiB
__device__ float g_hpart[4][B * DH * TC];       // 4 MiB (split-K partials of h)
__device__ float g_gate[B * D * TC];            // 8 MiB

// ---------------------------------------------------------------------------
// Kernel 1: per (b,d) row — chunk sums of 16, inclusive scan, divide by count.
// pooled[b,d,j] = sum(x[b,d,0:16(j+1)]) / (16(j+1))
// One block per row, 512 threads (one chunk each).
// ---------------------------------------------------------------------------
__global__ void pool_kernel(const float* __restrict__ x) {
    int row = blockIdx.x;                      // b*D + d
    const float4* xr = reinterpret_cast<const float4*>(x) + (size_t)row * (T / 4);
    int j = threadIdx.x;                       // chunk index 0..511

    float4 a0 = xr[j * 4 + 0];
    float4 a1 = xr[j * 4 + 1];
    float4 a2 = xr[j * 4 + 2];
    float4 a3 = xr[j * 4 + 3];
    float s = ((a0.x + a0.y) + (a0.z + a0.w)) + ((a1.x + a1.y) + (a1.z + a1.w))
            + ((a2.x + a2.y) + (a2.z + a2.w)) + ((a3.x + a3.y) + (a3.z + a3.w));

    int lane = j & 31, warp = j >> 5;

    // warp inclusive scan
    float v = s;
    #pragma unroll
    for (int off = 1; off < 32; off <<= 1) {
        float n = __shfl_up_sync(0xffffffffu, v, off);
        if (lane >= off) v += n;
    }

    __shared__ float wsum[16];
    if (lane == 31) wsum[warp] = v;
    __syncthreads();
    if (warp == 0) {
        float w = (lane < 16) ? wsum[lane] : 0.f;
        #pragma unroll
        for (int off = 1; off < 16; off <<= 1) {
            float n = __shfl_up_sync(0xffffffffu, w, off);
            if (lane >= off) w += n;
        }
        if (lane < 16) wsum[lane] = w;
    }
    __syncthreads();

    float prefix = (warp > 0) ? wsum[warp - 1] : 0.f;
    float total  = v + prefix;
    g_pooled[(size_t)row * TC + j] = total / (float)(CS * (j + 1));
}

// ---------------------------------------------------------------------------
// Kernel 2a: GEMM1 split-K partials.
// h[b,o,t] (pre-bias/relu) = sum_d w1[o,d] * pooled[b,d,t]
// Block: one b, 128-wide t tile, 128-wide k slice (blockIdx.y selects slice).
// 256 threads, each accumulates 8 o x 4 t. Inner loop: 1 LDS.128 + 8 LDS
// (broadcast) per 32 FFMA -> FFMA bound.
// ---------------------------------------------------------------------------
__global__ void gemm1_kernel(const float* __restrict__ w1) {
    __shared__ float Ps[64 * 128];   // [d_local][t_local] 32 KiB
    __shared__ float W1s[64 * 64];   // [o][d_local]       16 KiB

    int tid = threadIdx.x;
    int t0 = blockIdx.x * 128;
    int k0 = blockIdx.y * 128;
    int b  = blockIdx.z;
    int warp = tid >> 5, lane = tid & 31;
    int obase = warp * 8;
    int tt = lane * 4;

    float acc[8][4];
    #pragma unroll
    for (int o = 0; o < 8; o++)
        #pragma unroll
        for (int q = 0; q < 4; q++) acc[o][q] = 0.f;

    for (int c = 0; c < 2; c++) {
        int kc = k0 + c * 64;
        for (int i = tid; i < 64 * 128; i += 256) {
            int d = i >> 7, t = i & 127;
            Ps[i] = g_pooled[((size_t)(b * D) + kc + d) * TC + t0 + t];
        }
        for (int i = tid; i < 64 * 64; i += 256) {
            int o = i >> 6, d = i & 63;
            W1s[i] = w1[o * D + kc + d];
        }
        __syncthreads();

        #pragma unroll 4
        for (int dd = 0; dd < 64; dd++) {
            float4 p = *reinterpret_cast<const float4*>(&Ps[dd * 128 + tt]);
            #pragma unroll
            for (int o = 0; o < 8; o++) {
                float w = W1s[(obase + o) * 64 + dd];
                acc[o][0] = fmaf(w, p.x, acc[o][0]);
                acc[o][1] = fmaf(w, p.y, acc[o][1]);
                acc[o][2] = fmaf(w, p.z, acc[o][2]);
                acc[o][3] = fmaf(w, p.w, acc[o][3]);
            }
        }
        __syncthreads();
    }

    float* hp = g_hpart[blockIdx.y];
    #pragma unroll
    for (int o = 0; o < 8; o++) {
        float4 v = make_float4(acc[o][0], acc[o][1], acc[o][2], acc[o][3]);
        *reinterpret_cast<float4*>(&hp[((size_t)(b * DH) + obase + o) * TC + t0 + tt]) = v;
    }
}

// ---------------------------------------------------------------------------
// Kernel 2b: reduce split-K partials + b1 + relu into smem, then
// g[b,o,t] = sigmoid(sum_k w2[o,k]*h[b,k,t] + b2[o])
// Block: one b, 64-wide o tile, 128-wide t tile. 256 threads, 8o x 4t each.
// ---------------------------------------------------------------------------
__global__ void gemm2_kernel(const float* __restrict__ w2,
                             const float* __restrict__ b1,
                             const float* __restrict__ b2) {
    __shared__ float Hs[64 * 128];   // [k][t_local] 32 KiB
    __shared__ float W2s[64 * 64];   // [o_local][k] 16 KiB

    int tid = threadIdx.x;
    int t0 = blockIdx.x * 128;
    int o0 = blockIdx.y * 64;
    int b  = blockIdx.z;

    for (int i = tid; i < 64 * 128; i += 256) {
        int k = i >> 7, t = i & 127;
        size_t idx = ((size_t)(b * DH) + k) * TC + t0 + t;
        float v = g_hpart[0][idx] + g_hpart[1][idx]
                + g_hpart[2][idx] + g_hpart[3][idx] + b1[k];
        Hs[i] = fmaxf(v, 0.f);
    }
    for (int i = tid; i < 64 * 64; i += 256) {
        int o = i >> 6, k = i & 63;
        W2s[i] = w2[(o0 + o) * DH + k];
    }
    __syncthreads();

    int warp = tid >> 5, lane = tid & 31;
    int obase = warp * 8;
    int tt = lane * 4;

    float acc[8][4];
    #pragma unroll
    for (int o = 0; o < 8; o++)
        #pragma unroll
        for (int q = 0; q < 4; q++) acc[o][q] = 0.f;

    #pragma unroll 4
    for (int k = 0; k < 64; k++) {
        float4 h = *reinterpret_cast<const float4*>(&Hs[k * 128 + tt]);
        #pragma unroll
        for (int o = 0; o < 8; o++) {
            float w = W2s[(obase + o) * 64 + k];
            acc[o][0] = fmaf(w, h.x, acc[o][0]);
            acc[o][1] = fmaf(w, h.y, acc[o][1]);
            acc[o][2] = fmaf(w, h.z, acc[o][2]);
            acc[o][3] = fmaf(w, h.w, acc[o][3]);
        }
    }

    #pragma unroll
    for (int o = 0; o < 8; o++) {
        float bb = b2[o0 + obase + o];
        float4 g;
        g.x = 1.f / (1.f + __expf(-(acc[o][0] + bb)));
        g.y = 1.f / (1.f + __expf(-(acc[o][1] + bb)));
        g.z = 1.f / (1.f + __expf(-(acc[o][2] + bb)));
        g.w = 1.f / (1.f + __expf(-(acc[o][3] + bb)));
        *reinterpret_cast<float4*>(
            &g_gate[((size_t)(b * D) + o0 + obase + o) * TC + t0 + tt]) = g;
    }
}

// ---------------------------------------------------------------------------
// Kernel 3: out = repeat(g,16) * x, fully coalesced float4.
// ---------------------------------------------------------------------------
__global__ void scale_kernel(const float* __restrict__ x, float* __restrict__ out) {
    size_t i = (size_t)blockIdx.x * blockDim.x + threadIdx.x;   // float4 index
    const float4* x4 = reinterpret_cast<const float4*>(x);
    float4* o4 = reinterpret_cast<float4*>(out);
    float4 xv = x4[i];
    size_t row = i >> 11;               // / (T/4)
    size_t c   = (i & 2047) >> 2;       // chunk index = (t/4)/4
    float g = g_gate[row * TC + c];
    o4[i] = make_float4(xv.x * g, xv.y * g, xv.z * g, xv.w * g);
}

// ---------------------------------------------------------------------------
extern "C" void kernel_launch(void* const* d_in, const int* in_sizes, int n_in,
                              void* d_out, int out_size) {
    const float* x  = (const float*)d_in[0];
    const float* w1 = (const float*)d_in[1];
    const float* b1 = (const float*)d_in[2];
    const float* w2 = (const float*)d_in[3];
    const float* b2 = (const float*)d_in[4];
    float* out = (float*)d_out;

    pool_kernel<<<B * D, 512>>>(x);
    gemm1_kernel<<<dim3(4, 4, B), 256>>>(w1);
    gemm2_kernel<<<dim3(4, 8, B), 256>>>(w2, b1, b2);
    scale_kernel<<<(size_t)B * D * T / 4 / 256, 256>>>(x, out);
}

// round 2
// speedup vs baseline: 1.0411x; 1.0411x over previous
#include <cuda_runtime.h>

#define B  8
#define D  512
#define T  8192
#define CS 16
#define TC 512   // T / CS
#define DH 64    // D / 8

// Scratch (no cudaMalloc allowed)
__device__ float g_pooled[B * D * TC];          // 8 MiB
__device__ float g_hpart[4][B * DH * TC];       // 4 MiB x4 (split-K partials of h)
__device__ float g_gate[B * D * TC];            // 8 MiB

// ---------------------------------------------------------------------------
// Kernel 1: per (b,d) row — chunk sums of 16, inclusive scan, divide by count.
// pooled[b,d,j] = sum(x[b,d,0:16(j+1)]) / (16(j+1))
// One block per row, 512 threads. COALESCED: thread j loads float4 at
// block-stride offsets j, j+512, j+1024, j+1536 (512B contiguous per warp),
// then lane-groups of 4 reduce each 16-float chunk via shfl_xor.
// ---------------------------------------------------------------------------
__global__ void pool_kernel(const float* __restrict__ x) {
    int row = blockIdx.x;                      // b*D + d
    const float4* xr = reinterpret_cast<const float4*>(x) + (size_t)row * (T / 4);
    int j = threadIdx.x;

    __shared__ float csum[TC];
    __shared__ float wsum[16];

    // Front-batched coalesced loads (MLP=4)
    float4 f0 = xr[j];
    float4 f1 = xr[j + 512];
    float4 f2 = xr[j + 1024];
    float4 f3 = xr[j + 1536];

    float s0 = (f0.x + f0.y) + (f0.z + f0.w);
    float s1 = (f1.x + f1.y) + (f1.z + f1.w);
    float s2 = (f2.x + f2.y) + (f2.z + f2.w);
    float s3 = (f3.x + f3.y) + (f3.z + f3.w);

    // Reduce within lane-groups of 4 (chunk = float4_idx >> 2)
    s0 += __shfl_xor_sync(0xffffffffu, s0, 1);
    s0 += __shfl_xor_sync(0xffffffffu, s0, 2);
    s1 += __shfl_xor_sync(0xffffffffu, s1, 1);
    s1 += __shfl_xor_sync(0xffffffffu, s1, 2);
    s2 += __shfl_xor_sync(0xffffffffu, s2, 1);
    s2 += __shfl_xor_sync(0xffffffffu, s2, 2);
    s3 += __shfl_xor_sync(0xffffffffu, s3, 1);
    s3 += __shfl_xor_sync(0xffffffffu, s3, 2);

    if ((j & 3) == 0) {
        int c = j >> 2;                 // 0..127
        csum[c +   0] = s0;
        csum[c + 128] = s1;
        csum[c + 256] = s2;
        csum[c + 384] = s3;
    }
    __syncthreads();

    // Inclusive scan of 512 chunk sums
    int lane = j & 31, warp = j >> 5;
    float v = csum[j];
    #pragma unroll
    for (int off = 1; off < 32; off <<= 1) {
        float n = __shfl_up_sync(0xffffffffu, v, off);
        if (lane >= off) v += n;
    }
    if (lane == 31) wsum[warp] = v;
    __syncthreads();
    if (warp == 0) {
        float w = (lane < 16) ? wsum[lane] : 0.f;
        #pragma unroll
        for (int off = 1; off < 16; off <<= 1) {
            float n = __shfl_up_sync(0xffffffffu, w, off);
            if (lane >= off) w += n;
        }
        if (lane < 16) wsum[lane] = w;
    }
    __syncthreads();

    float prefix = (warp > 0) ? wsum[warp - 1] : 0.f;
    float total  = v + prefix;
    g_pooled[(size_t)row * TC + j] = total / (float)(CS * (j + 1));
}

// ---------------------------------------------------------------------------
// Kernel 2a: GEMM1 split-K partials.
// h_partial[s][b,o,t] = sum_{d in slice s} w1[o,d] * pooled[b,d,t]
// ---------------------------------------------------------------------------
__global__ void gemm1_kernel(const float* __restrict__ w1) {
    __shared__ float Ps[64 * 128];   // [d_local][t_local] 32 KiB
    __shared__ float W1s[64 * 64];   // [o][d_local]       16 KiB

    int tid = threadIdx.x;
    int t0 = blockIdx.x * 128;
    int k0 = blockIdx.y * 128;
    int b  = blockIdx.z;
    int warp = tid >> 5, lane = tid & 31;
    int obase = warp * 8;
    int tt = lane * 4;

    float acc[8][4];
    #pragma unroll
    for (int o = 0; o < 8; o++)
        #pragma unroll
        for (int q = 0; q < 4; q++) acc[o][q] = 0.f;

    for (int c = 0; c < 2; c++) {
        int kc = k0 + c * 64;
        for (int i = tid; i < 64 * 128; i += 256) {
            int d = i >> 7, t = i & 127;
            Ps[i] = g_pooled[((size_t)(b * D) + kc + d) * TC + t0 + t];
        }
        for (int i = tid; i < 64 * 64; i += 256) {
            int o = i >> 6, d = i & 63;
            W1s[i] = w1[o * D + kc + d];
        }
        __syncthreads();

        #pragma unroll 4
        for (int dd = 0; dd < 64; dd++) {
            float4 p = *reinterpret_cast<const float4*>(&Ps[dd * 128 + tt]);
            #pragma unroll
            for (int o = 0; o < 8; o++) {
                float w = W1s[(obase + o) * 64 + dd];
                acc[o][0] = fmaf(w, p.x, acc[o][0]);
                acc[o][1] = fmaf(w, p.y, acc[o][1]);
                acc[o][2] = fmaf(w, p.z, acc[o][2]);
                acc[o][3] = fmaf(w, p.w, acc[o][3]);
            }
        }
        __syncthreads();
    }

    float* hp = g_hpart[blockIdx.y];
    #pragma unroll
    for (int o = 0; o < 8; o++) {
        float4 v = make_float4(acc[o][0], acc[o][1], acc[o][2], acc[o][3]);
        *reinterpret_cast<float4*>(&hp[((size_t)(b * DH) + obase + o) * TC + t0 + tt]) = v;
    }
}

// ---------------------------------------------------------------------------
// Kernel 2b: reduce split-K partials + b1 + relu into smem, then
// g[b,o,t] = sigmoid(sum_k w2[o,k]*h[b,k,t] + b2[o])
// ---------------------------------------------------------------------------
__global__ void gemm2_kernel(const float* __restrict__ w2,
                             const float* __restrict__ b1,
                             const float* __restrict__ b2) {
    __shared__ float Hs[64 * 128];   // [k][t_local] 32 KiB
    __shared__ float W2s[64 * 64];   // [o_local][k] 16 KiB

    int tid = threadIdx.x;
    int t0 = blockIdx.x * 128;
    int o0 = blockIdx.y * 64;
    int b  = blockIdx.z;

    for (int i = tid; i < 64 * 128; i += 256) {
        int k = i >> 7, t = i & 127;
        size_t idx = ((size_t)(b * DH) + k) * TC + t0 + t;
        float v = g_hpart[0][idx] + g_hpart[1][idx]
                + g_hpart[2][idx] + g_hpart[3][idx] + b1[k];
        Hs[i] = fmaxf(v, 0.f);
    }
    for (int i = tid; i < 64 * 64; i += 256) {
        int o = i >> 6, k = i & 63;
        W2s[i] = w2[(o0 + o) * DH + k];
    }
    __syncthreads();

    int warp = tid >> 5, lane = tid & 31;
    int obase = warp * 8;
    int tt = lane * 4;

    float acc[8][4];
    #pragma unroll
    for (int o = 0; o < 8; o++)
        #pragma unroll
        for (int q = 0; q < 4; q++) acc[o][q] = 0.f;

    #pragma unroll 4
    for (int k = 0; k < 64; k++) {
        float4 h = *reinterpret_cast<const float4*>(&Hs[k * 128 + tt]);
        #pragma unroll
        for (int o = 0; o < 8; o++) {
            float w = W2s[(obase + o) * 64 + k];
            acc[o][0] = fmaf(w, h.x, acc[o][0]);
            acc[o][1] = fmaf(w, h.y, acc[o][1]);
            acc[o][2] = fmaf(w, h.z, acc[o][2]);
            acc[o][3] = fmaf(w, h.w, acc[o][3]);
        }
    }

    #pragma unroll
    for (int o = 0; o < 8; o++) {
        float bb = b2[o0 + obase + o];
        float4 g;
        g.x = 1.f / (1.f + __expf(-(acc[o][0] + bb)));
        g.y = 1.f / (1.f + __expf(-(acc[o][1] + bb)));
        g.z = 1.f / (1.f + __expf(-(acc[o][2] + bb)));
        g.w = 1.f / (1.f + __expf(-(acc[o][3] + bb)));
        *reinterpret_cast<float4*>(
            &g_gate[((size_t)(b * D) + o0 + obase + o) * TC + t0 + tt]) = g;
    }
}

// ---------------------------------------------------------------------------
// Kernel 3: out = repeat(g,16) * x. Coalesced float4, 4-way ILP grid-stride.
// ---------------------------------------------------------------------------
__global__ void scale_kernel(const float* __restrict__ x, float* __restrict__ out) {
    const float4* x4 = reinterpret_cast<const float4*>(x);
    float4* o4 = reinterpret_cast<float4*>(out);
    size_t base = (size_t)blockIdx.x * blockDim.x + threadIdx.x;
    const size_t stride = (size_t)gridDim.x * blockDim.x;   // total/4

    float4 xv[4];
    float  g[4];
    #pragma unroll
    for (int k = 0; k < 4; k++) {
        size_t i = base + (size_t)k * stride;
        xv[k] = x4[i];
    }
    #pragma unroll
    for (int k = 0; k < 4; k++) {
        size_t i = base + (size_t)k * stride;
        size_t row = i >> 11;               // / (T/4)
        size_t c   = (i & 2047) >> 2;       // chunk index
        g[k] = g_gate[row * TC + c];
    }
    #pragma unroll
    for (int k = 0; k < 4; k++) {
        size_t i = base + (size_t)k * stride;
        o4[i] = make_float4(xv[k].x * g[k], xv[k].y * g[k],
                            xv[k].z * g[k], xv[k].w * g[k]);
    }
}

// ---------------------------------------------------------------------------
extern "C" void kernel_launch(void* const* d_in, const int* in_sizes, int n_in,
                              void* d_out, int out_size) {
    const float* x  = (const float*)d_in[0];
    const float* w1 = (const float*)d_in[1];
    const float* b1 = (const float*)d_in[2];
    const float* w2 = (const float*)d_in[3];
    const float* b2 = (const float*)d_in[4];
    float* out = (float*)d_out;

    pool_kernel<<<B * D, 512>>>(x);
    gemm1_kernel<<<dim3(4, 4, B), 256>>>(w1);
    gemm2_kernel<<<dim3(4, 8, B), 256>>>(w2, b1, b2);
    // total float4 = B*D*T/4 = 8388608; 4 per thread, 256 threads/block
    scale_kernel<<<8192, 256>>>(x, out);
}